// round 6
// baseline (speedup 1.0000x reference)
#include <cuda_runtime.h>

// RadarNet R6: single fused kernel, one 128-thread block per row.
//   phase 0: load x, G = W1@W2 per block
//   phase 1: lag sums (smem-tree reduction) -> means -> C via 20 diagonal scans
//   phase 2: S2 = G^T C G   [ReEig certified no-op]
//   phase 3: warp 0: 8x8 shuffle Jacobi LogEig + linear head (R2-proven).

namespace {
constexpr int   TLEN = 512;
constexpr int   WINW = 20;
constexpr int   NW   = 493;
constexpr int   D2   = 8;
}

__global__ __launch_bounds__(128)
void radarnet_fused_kernel(const float* __restrict__ gx,
                           const float* __restrict__ gW1,
                           const float* __restrict__ gW2,
                           const float* __restrict__ gWl,
                           const float* __restrict__ gbl,
                           float* __restrict__ out)
{
    __shared__ __align__(16) float xs[544];
    __shared__ float part[128 * 21];         // per-lane lag partials
    __shared__ float rsum[21 * 6];
    __shared__ float Gs[WINW * D2];
    __shared__ float Cm[WINW][WINW + 1];
    __shared__ float Tg[WINW][D2];
    __shared__ float lag[21];
    __shared__ float mw[WINW];
    __shared__ float wls[192];
    __shared__ float bls[3];
    __shared__ float S2s[64];
    __shared__ float Vd[72];
    __shared__ float al8[8], be8[8];
    __shared__ int   prr[8];

    const int tid = threadIdx.x;
    const int b   = blockIdx.x;
    const unsigned FULL = 0xffffffffu;

    // ---------- phase 0 ----------
    {
        float4 v = reinterpret_cast<const float4*>(gx + b * TLEN)[tid];
        reinterpret_cast<float4*>(xs)[tid] = v;
    }
    if (tid < 32) xs[512 + tid] = 0.f;
    for (int t = tid; t < WINW * D2; t += 128) {
        int w = t >> 3, c = t & 7;
        float s = 0.f;
        #pragma unroll
        for (int i = 0; i < 16; ++i) s = fmaf(gW1[w * 16 + i], gW2[i * 8 + c], s);
        Gs[t] = s;
    }
    for (int t = tid; t < 192; t += 128) wls[t] = gWl[t];
    if (tid < 3) bls[tid] = gbl[tid];
    __syncthreads();

    // ---------- phase 1a: per-lane lag partials ----------
    float acc[21];
    #pragma unroll
    for (int d = 0; d < 21; ++d) acc[d] = 0.f;
    if (tid < 124) {
        const float4* x4 = reinterpret_cast<const float4*>(xs);
        float xv[24];
        #pragma unroll
        for (int q = 0; q < 6; ++q) {
            float4 v = x4[tid + q];
            xv[4*q+0] = v.x; xv[4*q+1] = v.y; xv[4*q+2] = v.z; xv[4*q+3] = v.w;
        }
        #pragma unroll
        for (int k = 0; k < 4; ++k) {
            if (4 * tid + k <= NW - 1) {
                float xk = xv[k];
                #pragma unroll
                for (int d = 0; d < WINW; ++d) acc[d] = fmaf(xk, xv[k + d], acc[d]);
                acc[20] += xk;
            }
        }
    }
    // lane-major store: addr = 21*tid + d  (stride 21 -> conflict-free)
    #pragma unroll
    for (int d = 0; d < 21; ++d) part[tid * 21 + d] = acc[d];
    __syncthreads();

    // ---------- phase 1b: tree stage 1 (126 threads, 22-row chunks) ----------
    if (tid < 126) {
        int d = tid / 6, k = tid - d * 6;
        int j0 = k * 22;
        int j1 = j0 + 22; if (j1 > 128) j1 = 128;
        float s0 = 0.f, s1 = 0.f;
        #pragma unroll 1
        for (int j = j0; j + 1 < j1; j += 2) {
            s0 += part[j * 21 + d];
            s1 += part[(j + 1) * 21 + d];
        }
        if ((j1 - j0) & 1) s0 += part[(j1 - 1) * 21 + d];
        rsum[d * 6 + k] = s0 + s1;
    }
    __syncthreads();

    // ---------- phase 1c: warp 0 folds lags + window means scan ----------
    if (tid < 32) {
        if (tid < 21) {
            float s = 0.f;
            #pragma unroll
            for (int k = 0; k < 6; ++k) s += rsum[tid * 6 + k];
            lag[tid] = s;
        }
        __syncwarp();
        float sum0 = lag[20];
        float val  = 0.f;
        if (tid >= 1 && tid < WINW) val = xs[NW - 1 + tid] - xs[tid - 1];
        #pragma unroll
        for (int o = 1; o < 32; o <<= 1) {
            float t = __shfl_up_sync(FULL, val, o);
            if (tid >= o) val += t;
        }
        if (tid < WINW) mw[tid] = (sum0 + val) * (1.f / (float)NW);
    }
    __syncthreads();

    // ---------- phase 1d: C via 20 diagonal scans (5 lanes per warp) ----------
    {
        const int lw = tid & 31, wr = tid >> 5;
        if (lw < 5) {
            const int d = wr * 5 + lw;             // 0..19
            const float inv = 1.f / (float)(NW - 1);
            float s = lag[d];
            float cv = (s - (float)NW * mw[0] * mw[d]) * inv;
            Cm[0][d] = cv; Cm[d][0] = cv;
            #pragma unroll 1
            for (int w = 1; w + d < WINW; ++w) {
                s += xs[NW - 1 + w] * xs[NW - 1 + w + d] - xs[w - 1] * xs[w - 1 + d];
                cv = (s - (float)NW * mw[w] * mw[w + d]) * inv;
                Cm[w][w + d] = cv; Cm[w + d][w] = cv;
            }
        }
    }
    __syncthreads();

    // ---------- phase 2: Tg = C*G, S2 = G^T*Tg ----------
    for (int t = tid; t < WINW * D2; t += 128) {
        int w = t >> 3, c = t & 7;
        float s = 0.f;
        #pragma unroll
        for (int v2 = 0; v2 < WINW; ++v2) s = fmaf(Cm[w][v2], Gs[v2 * 8 + c], s);
        Tg[w][c] = s;
    }
    __syncthreads();
    if (tid < 64) {
        int a = tid >> 3, c = tid & 7;
        float s = 0.f;
        #pragma unroll
        for (int w = 0; w < WINW; ++w) s = fmaf(Gs[w * 8 + a], Tg[w][c], s);
        S2s[tid] = s;
    }
    __syncthreads();

    // ---------- phase 3: warp 0 only — LogEig + head ----------
    if (tid >= 32) return;
    const int l = tid;
    const int i4 = l >> 3, j8 = l & 7;
    float a0 = S2s[i4 * 8 + j8];
    float a1 = S2s[(i4 + 4) * 8 + j8];
    float v0 = (i4 == j8) ? 1.f : 0.f;
    float v1 = (i4 + 4 == j8) ? 1.f : 0.f;

    for (int sweep = 0; sweep < 10; ++sweep) {
        for (int rr = 0; rr < 7; ++rr) {
            int k  = l & 3;
            int sa = (k == 0) ? 0 : ((k - 1 + rr) % 7) + 1;
            int sb = ((6 - k + rr) % 7) + 1;
            int p = sa < sb ? sa : sb, q = sa < sb ? sb : sa;
            int srcpp = (p & 3) * 8 + p;
            int srcqq = (q & 3) * 8 + q;
            int srcpq = (p & 3) * 8 + q;
            float pp0 = __shfl_sync(FULL, a0, srcpp), pp1 = __shfl_sync(FULL, a1, srcpp);
            float qq0 = __shfl_sync(FULL, a0, srcqq), qq1 = __shfl_sync(FULL, a1, srcqq);
            float pq0 = __shfl_sync(FULL, a0, srcpq), pq1 = __shfl_sync(FULL, a1, srcpq);
            if (l < 4) {
                float app = (p >= 4) ? pp1 : pp0;
                float aqq = (q >= 4) ? qq1 : qq0;
                float apq = (p >= 4) ? pq1 : pq0;
                float c, sn;
                if (fabsf(apq) < 1e-12f) { c = 1.f; sn = 0.f; }
                else {
                    float th = __fdividef(aqq - app, 2.f * apq);
                    float t  = __fdividef(1.f, fabsf(th) + sqrtf(fmaf(th, th, 1.f)));
                    if (th < 0.f) t = -t;
                    c = rsqrtf(fmaf(t, t, 1.f)); sn = t * c;
                }
                al8[p] = c; be8[p] = -sn; prr[p] = q;
                al8[q] = c; be8[q] =  sn; prr[q] = p;
            }
            __syncwarp();
            int   ra = i4, rb = i4 + 4;
            int   pa = prr[ra], pb = prr[rb];
            float ala = al8[ra], bea = be8[ra];
            float alb = al8[rb], beb = be8[rb];
            int   sa0 = (pa & 3) * 8 + j8, sb0 = (pb & 3) * 8 + j8;
            float u00 = __shfl_sync(FULL, a0, sa0), u01 = __shfl_sync(FULL, a1, sa0);
            float u10 = __shfl_sync(FULL, a0, sb0), u11 = __shfl_sync(FULL, a1, sb0);
            float xa = (pa >= 4) ? u01 : u00;
            float xb = (pb >= 4) ? u11 : u10;
            a0 = fmaf(ala, a0, bea * xa);
            a1 = fmaf(alb, a1, beb * xb);
            int   pj = prr[j8];
            float alj = al8[j8], bej = be8[j8];
            int   sc = (l & 24) + pj;
            float b0 = __shfl_sync(FULL, a0, sc), b1 = __shfl_sync(FULL, a1, sc);
            float w0 = __shfl_sync(FULL, v0, sc), w1 = __shfl_sync(FULL, v1, sc);
            a0 = fmaf(alj, a0, bej * b0); a1 = fmaf(alj, a1, bej * b1);
            v0 = fmaf(alj, v0, bej * w0); v1 = fmaf(alj, v1, bej * w1);
        }
        float off = ((i4 != j8) ? a0 * a0 : 0.f) + ((i4 + 4 != j8) ? a1 * a1 : 0.f);
        #pragma unroll
        for (int o = 16; o; o >>= 1) off += __shfl_xor_sync(FULL, off, o);
        if (off < 1e-11f) break;
    }

    __syncwarp();
    if (j8 == i4)     Vd[64 + i4]     = logf(fmaxf(a0, 1e-30f));
    if (j8 == i4 + 4) Vd[64 + i4 + 4] = logf(fmaxf(a1, 1e-30f));
    Vd[i4 * 8 + j8]       = v0;
    Vd[(i4 + 4) * 8 + j8] = v1;
    __syncwarp();

    float L0 = 0.f, L1 = 0.f;
    #pragma unroll
    for (int k = 0; k < 8; ++k) {
        float lgv = Vd[64 + k];
        float vjk = Vd[j8 * 8 + k];
        L0 = fmaf(Vd[i4 * 8 + k] * lgv,       vjk, L0);
        L1 = fmaf(Vd[(i4 + 4) * 8 + k] * lgv, vjk, L1);
    }
    int f0 = i4 * 8 + j8, f1 = (i4 + 4) * 8 + j8;
    float o0 = L0 * wls[f0]       + L1 * wls[f1];
    float o1 = L0 * wls[64 + f0]  + L1 * wls[64 + f1];
    float o2 = L0 * wls[128 + f0] + L1 * wls[128 + f1];
    #pragma unroll
    for (int o = 16; o; o >>= 1) {
        o0 += __shfl_xor_sync(FULL, o0, o);
        o1 += __shfl_xor_sync(FULL, o1, o);
        o2 += __shfl_xor_sync(FULL, o2, o);
    }
    if (l == 0) {
        out[b * 3 + 0] = o0 + bls[0];
        out[b * 3 + 1] = o1 + bls[1];
        out[b * 3 + 2] = o2 + bls[2];
    }
}

extern "C" void kernel_launch(void* const* d_in, const int* in_sizes, int n_in,
                              void* d_out, int out_size)
{
    const float* x    = (const float*)d_in[0];
    const float* W1   = (const float*)d_in[1];
    const float* W2   = (const float*)d_in[2];
    const float* Wlin = (const float*)d_in[3];
    const float* blin = (const float*)d_in[4];
    float* out = (float*)d_out;

    const int B = in_sizes[0] / TLEN;     // 8192
    radarnet_fused_kernel<<<B, 128>>>(x, W1, W2, Wlin, blin, out);
}

// round 7
// speedup vs baseline: 1.1027x; 1.1027x over previous
#include <cuda_runtime.h>

// RadarNet R7: single fused kernel, one 128-thread block per row. R5 structure,
// with the C-matrix build replaced by products + warp-parallel prefix scans:
//   phase 0: load x, G = W1@W2 per block
//   phase 1: lag partials + butterfly; then (warp0: fold+means scan) ||
//            (warps1-3: term(u,d) products); then 20 shfl prefix scans -> C
//   phase 2: S2 = G^T C G   [ReEig certified no-op]
//   phase 3: warp 0: 8x8 shuffle Jacobi LogEig + linear head (proven code).

namespace {
constexpr int   TLEN = 512;
constexpr int   WINW = 20;
constexpr int   NW   = 493;
constexpr int   D2   = 8;
}

__global__ __launch_bounds__(128)
void radarnet_fused_kernel(const float* __restrict__ gx,
                           const float* __restrict__ gW1,
                           const float* __restrict__ gW2,
                           const float* __restrict__ gWl,
                           const float* __restrict__ gbl,
                           float* __restrict__ out)
{
    __shared__ __align__(16) float xs[544];
    __shared__ float Gs[WINW * D2];
    __shared__ float Cm[WINW][WINW + 1];
    __shared__ float Tg[WINW][D2];
    __shared__ float lagw[4][21];
    __shared__ float lag[21];
    __shared__ float mw[WINW];
    __shared__ float term[19 * 20];          // term[u-1][d], u in [1,19]
    __shared__ float wls[192];
    __shared__ float bls[3];
    __shared__ float S2s[64];
    __shared__ float Vd[72];
    __shared__ float al8[8], be8[8];
    __shared__ int   prr[8];

    const int tid = threadIdx.x;
    const int b   = blockIdx.x;
    const unsigned FULL = 0xffffffffu;

    // ---------- phase 0 ----------
    {
        float4 v = reinterpret_cast<const float4*>(gx + b * TLEN)[tid];
        reinterpret_cast<float4*>(xs)[tid] = v;
    }
    if (tid < 32) xs[512 + tid] = 0.f;
    for (int t = tid; t < WINW * D2; t += 128) {
        int w = t >> 3, c = t & 7;
        float s = 0.f;
        #pragma unroll
        for (int i = 0; i < 16; ++i) s = fmaf(gW1[w * 16 + i], gW2[i * 8 + c], s);
        Gs[t] = s;
    }
    for (int t = tid; t < 192; t += 128) wls[t] = gWl[t];
    if (tid < 3) bls[tid] = gbl[tid];
    __syncthreads();

    // ---------- phase 1a: lag partials + warp butterfly (R5-proven) ----------
    float acc[21];
    #pragma unroll
    for (int d = 0; d < 21; ++d) acc[d] = 0.f;
    if (tid < 124) {
        const float4* x4 = reinterpret_cast<const float4*>(xs);
        float xv[24];
        #pragma unroll
        for (int q = 0; q < 6; ++q) {
            float4 v = x4[tid + q];
            xv[4*q+0] = v.x; xv[4*q+1] = v.y; xv[4*q+2] = v.z; xv[4*q+3] = v.w;
        }
        #pragma unroll
        for (int k = 0; k < 4; ++k) {
            if (4 * tid + k <= NW - 1) {
                float xk = xv[k];
                #pragma unroll
                for (int d = 0; d < WINW; ++d) acc[d] = fmaf(xk, xv[k + d], acc[d]);
                acc[20] += xk;
            }
        }
    }
    {
        #pragma unroll
        for (int d = 0; d < 21; ++d) {
            float v = acc[d];
            #pragma unroll
            for (int o = 16; o; o >>= 1) v += __shfl_down_sync(FULL, v, o);
            if ((tid & 31) == 0) lagw[tid >> 5][d] = v;
        }
    }
    __syncthreads();

    // ---------- phase 1b: warp0 (fold + means) || warps1-3 (term products) ----
    if (tid < 32) {
        if (tid < 21) lag[tid] = lagw[0][tid] + lagw[1][tid] + lagw[2][tid] + lagw[3][tid];
        __syncwarp();
        float sum0 = lag[20];
        float val  = 0.f;
        if (tid >= 1 && tid < WINW) val = xs[NW - 1 + tid] - xs[tid - 1];
        #pragma unroll
        for (int o = 1; o < 32; o <<= 1) {
            float t = __shfl_up_sync(FULL, val, o);
            if (tid >= o) val += t;
        }
        if (tid < WINW) mw[tid] = (sum0 + val) * (1.f / (float)NW);
    } else {
        // 380 products over 96 threads: term(u,d) = x[NW-1+u]x[NW-1+u+d] - x[u-1]x[u-1+d]
        int t0 = tid - 32;
        #pragma unroll
        for (int jj = 0; jj < 4; ++jj) {
            int idx = t0 + 96 * jj;
            if (idx < 380) {
                int u = idx / 20 + 1;            // 1..19
                int d = idx - (u - 1) * 20;      // 0..19
                float tp = xs[NW - 1 + u] * xs[NW - 1 + u + d];
                float tm = xs[u - 1]      * xs[u - 1 + d];
                term[idx] = tp - tm;
            }
        }
    }
    __syncthreads();

    // ---------- phase 1c: 20 prefix scans (5 per warp) -> C ----------
    {
        const int lw = tid & 31, wr = tid >> 5;
        const float inv = 1.f / (float)(NW - 1);
        #pragma unroll
        for (int k = 0; k < 5; ++k) {
            const int d = wr * 5 + k;            // 0..19
            // lane lw == w; term for u=w (w>=1)
            float v = (lw >= 1 && lw <= 19) ? term[(lw - 1) * 20 + d] : 0.f;
            #pragma unroll
            for (int o = 1; o < 32; o <<= 1) {
                float t = __shfl_up_sync(FULL, v, o);
                if (lw >= o) v += t;
            }
            if (lw + d < WINW) {
                float cv = (lag[d] + v - (float)NW * mw[lw] * mw[lw + d]) * inv;
                Cm[lw][lw + d] = cv;
                Cm[lw + d][lw] = cv;
            }
        }
    }
    __syncthreads();

    // ---------- phase 2: Tg = C*G, S2 = G^T*Tg ----------
    for (int t = tid; t < WINW * D2; t += 128) {
        int w = t >> 3, c = t & 7;
        float s = 0.f;
        #pragma unroll
        for (int v2 = 0; v2 < WINW; ++v2) s = fmaf(Cm[w][v2], Gs[v2 * 8 + c], s);
        Tg[w][c] = s;
    }
    __syncthreads();
    if (tid < 64) {
        int a = tid >> 3, c = tid & 7;
        float s = 0.f;
        #pragma unroll
        for (int w = 0; w < WINW; ++w) s = fmaf(Gs[w * 8 + a], Tg[w][c], s);
        S2s[tid] = s;
    }
    __syncthreads();

    // ---------- phase 3: warp 0 only — LogEig + head (R5-proven) ----------
    if (tid >= 32) return;
    const int l = tid;
    const int i4 = l >> 3, j8 = l & 7;
    float a0 = S2s[i4 * 8 + j8];
    float a1 = S2s[(i4 + 4) * 8 + j8];
    float v0 = (i4 == j8) ? 1.f : 0.f;
    float v1 = (i4 + 4 == j8) ? 1.f : 0.f;

    for (int sweep = 0; sweep < 10; ++sweep) {
        for (int rr = 0; rr < 7; ++rr) {
            int k  = l & 3;
            int sa = (k == 0) ? 0 : ((k - 1 + rr) % 7) + 1;
            int sb = ((6 - k + rr) % 7) + 1;
            int p = sa < sb ? sa : sb, q = sa < sb ? sb : sa;
            int srcpp = (p & 3) * 8 + p;
            int srcqq = (q & 3) * 8 + q;
            int srcpq = (p & 3) * 8 + q;
            float pp0 = __shfl_sync(FULL, a0, srcpp), pp1 = __shfl_sync(FULL, a1, srcpp);
            float qq0 = __shfl_sync(FULL, a0, srcqq), qq1 = __shfl_sync(FULL, a1, srcqq);
            float pq0 = __shfl_sync(FULL, a0, srcpq), pq1 = __shfl_sync(FULL, a1, srcpq);
            if (l < 4) {
                float app = (p >= 4) ? pp1 : pp0;
                float aqq = (q >= 4) ? qq1 : qq0;
                float apq = (p >= 4) ? pq1 : pq0;
                float c, sn;
                if (fabsf(apq) < 1e-12f) { c = 1.f; sn = 0.f; }
                else {
                    float th = __fdividef(aqq - app, 2.f * apq);
                    float t  = __fdividef(1.f, fabsf(th) + sqrtf(fmaf(th, th, 1.f)));
                    if (th < 0.f) t = -t;
                    c = rsqrtf(fmaf(t, t, 1.f)); sn = t * c;
                }
                al8[p] = c; be8[p] = -sn; prr[p] = q;
                al8[q] = c; be8[q] =  sn; prr[q] = p;
            }
            __syncwarp();
            int   ra = i4, rb = i4 + 4;
            int   pa = prr[ra], pb = prr[rb];
            float ala = al8[ra], bea = be8[ra];
            float alb = al8[rb], beb = be8[rb];
            int   sa0 = (pa & 3) * 8 + j8, sb0 = (pb & 3) * 8 + j8;
            float u00 = __shfl_sync(FULL, a0, sa0), u01 = __shfl_sync(FULL, a1, sa0);
            float u10 = __shfl_sync(FULL, a0, sb0), u11 = __shfl_sync(FULL, a1, sb0);
            float xa = (pa >= 4) ? u01 : u00;
            float xb = (pb >= 4) ? u11 : u10;
            a0 = fmaf(ala, a0, bea * xa);
            a1 = fmaf(alb, a1, beb * xb);
            int   pj = prr[j8];
            float alj = al8[j8], bej = be8[j8];
            int   sc = (l & 24) + pj;
            float b0 = __shfl_sync(FULL, a0, sc), b1 = __shfl_sync(FULL, a1, sc);
            float w0 = __shfl_sync(FULL, v0, sc), w1 = __shfl_sync(FULL, v1, sc);
            a0 = fmaf(alj, a0, bej * b0); a1 = fmaf(alj, a1, bej * b1);
            v0 = fmaf(alj, v0, bej * w0); v1 = fmaf(alj, v1, bej * w1);
        }
        float off = ((i4 != j8) ? a0 * a0 : 0.f) + ((i4 + 4 != j8) ? a1 * a1 : 0.f);
        #pragma unroll
        for (int o = 16; o; o >>= 1) off += __shfl_xor_sync(FULL, off, o);
        if (off < 1e-11f) break;
    }

    __syncwarp();
    if (j8 == i4)     Vd[64 + i4]     = logf(fmaxf(a0, 1e-30f));
    if (j8 == i4 + 4) Vd[64 + i4 + 4] = logf(fmaxf(a1, 1e-30f));
    Vd[i4 * 8 + j8]       = v0;
    Vd[(i4 + 4) * 8 + j8] = v1;
    __syncwarp();

    float L0 = 0.f, L1 = 0.f;
    #pragma unroll
    for (int k = 0; k < 8; ++k) {
        float lgv = Vd[64 + k];
        float vjk = Vd[j8 * 8 + k];
        L0 = fmaf(Vd[i4 * 8 + k] * lgv,       vjk, L0);
        L1 = fmaf(Vd[(i4 + 4) * 8 + k] * lgv, vjk, L1);
    }
    int f0 = i4 * 8 + j8, f1 = (i4 + 4) * 8 + j8;
    float o0 = L0 * wls[f0]       + L1 * wls[f1];
    float o1 = L0 * wls[64 + f0]  + L1 * wls[64 + f1];
    float o2 = L0 * wls[128 + f0] + L1 * wls[128 + f1];
    #pragma unroll
    for (int o = 16; o; o >>= 1) {
        o0 += __shfl_xor_sync(FULL, o0, o);
        o1 += __shfl_xor_sync(FULL, o1, o);
        o2 += __shfl_xor_sync(FULL, o2, o);
    }
    if (l == 0) {
        out[b * 3 + 0] = o0 + bls[0];
        out[b * 3 + 1] = o1 + bls[1];
        out[b * 3 + 2] = o2 + bls[2];
    }
}

extern "C" void kernel_launch(void* const* d_in, const int* in_sizes, int n_in,
                              void* d_out, int out_size)
{
    const float* x    = (const float*)d_in[0];
    const float* W1   = (const float*)d_in[1];
    const float* W2   = (const float*)d_in[2];
    const float* Wlin = (const float*)d_in[3];
    const float* blin = (const float*)d_in[4];
    float* out = (float*)d_out;

    const int B = in_sizes[0] / TLEN;     // 8192
    radarnet_fused_kernel<<<B, 128>>>(x, W1, W2, Wlin, blin, out);
}

// round 8
// speedup vs baseline: 1.4722x; 1.3351x over previous
#include <cuda_runtime.h>

// RadarNet R8: two kernels.
// K1: x -> lag sums -> means -> C(20,20) -> S2 = G^T C G (G=W1@W2) -> scratch.
//     (R5-proven cov pipeline, tail removed.)
// K2: 4 rows per warp, 8-lane groups: column-register 8x8 Jacobi with static
//     Brent-Luk schedule (R3-proven fast path; no ReEig fallback exists since
//     lambda_min(S1) >= lambda_min(C) >> 1e-4), head via quadratic forms.

namespace {
constexpr int   TLEN = 512;
constexpr int   WINW = 20;
constexpr int   NW   = 493;
constexpr int   D2   = 8;
constexpr int   MAXB = 8192;
}

__device__ float g_S2[MAXB * 64];

// ---------------------------------------------------------------------------
// Kernel 1: covariance + S2 (R5 phases 0-2)
// ---------------------------------------------------------------------------
__global__ __launch_bounds__(128)
void radar_cov_kernel(const float* __restrict__ gx,
                      const float* __restrict__ gW1,
                      const float* __restrict__ gW2)
{
    __shared__ __align__(16) float xs[544];
    __shared__ float Gs[WINW * D2];
    __shared__ float Cm[WINW][WINW + 1];
    __shared__ float Tg[WINW][D2];
    __shared__ float lagw[4][21];
    __shared__ float lag[21];
    __shared__ float mw[WINW];

    const int tid = threadIdx.x;
    const int b   = blockIdx.x;
    const unsigned FULL = 0xffffffffu;

    // ---------- phase 0: loads + G = W1@W2 ----------
    {
        float4 v = reinterpret_cast<const float4*>(gx + b * TLEN)[tid];
        reinterpret_cast<float4*>(xs)[tid] = v;
    }
    if (tid < 32) xs[512 + tid] = 0.f;
    for (int t = tid; t < WINW * D2; t += 128) {
        int w = t >> 3, c = t & 7;
        float s = 0.f;
        #pragma unroll
        for (int i = 0; i < 16; ++i) s = fmaf(gW1[w * 16 + i], gW2[i * 8 + c], s);
        Gs[t] = s;
    }
    __syncthreads();

    // ---------- phase 1a: lag partials + butterfly ----------
    float acc[21];
    #pragma unroll
    for (int d = 0; d < 21; ++d) acc[d] = 0.f;
    if (tid < 124) {
        const float4* x4 = reinterpret_cast<const float4*>(xs);
        float xv[24];
        #pragma unroll
        for (int q = 0; q < 6; ++q) {
            float4 v = x4[tid + q];
            xv[4*q+0] = v.x; xv[4*q+1] = v.y; xv[4*q+2] = v.z; xv[4*q+3] = v.w;
        }
        #pragma unroll
        for (int k = 0; k < 4; ++k) {
            if (4 * tid + k <= NW - 1) {
                float xk = xv[k];
                #pragma unroll
                for (int d = 0; d < WINW; ++d) acc[d] = fmaf(xk, xv[k + d], acc[d]);
                acc[20] += xk;
            }
        }
    }
    {
        #pragma unroll
        for (int d = 0; d < 21; ++d) {
            float v = acc[d];
            #pragma unroll
            for (int o = 16; o; o >>= 1) v += __shfl_down_sync(FULL, v, o);
            if ((tid & 31) == 0) lagw[tid >> 5][d] = v;
        }
    }
    __syncthreads();

    // ---------- phase 1b: fold + window-means scan (warp 0) ----------
    if (tid < 32) {
        if (tid < 21) lag[tid] = lagw[0][tid] + lagw[1][tid] + lagw[2][tid] + lagw[3][tid];
        __syncwarp();
        float sum0 = lag[20];
        float val  = 0.f;
        if (tid >= 1 && tid < WINW) val = xs[NW - 1 + tid] - xs[tid - 1];
        #pragma unroll
        for (int o = 1; o < 32; o <<= 1) {
            float t = __shfl_up_sync(FULL, val, o);
            if (tid >= o) val += t;
        }
        if (tid < WINW) mw[tid] = (sum0 + val) * (1.f / (float)NW);
    }
    __syncthreads();

    // ---------- phase 1c: C entries (210 pairs, prefix corrections) ----------
    for (int idx = tid; idx < 210; idx += 128) {
        int w = (int)(20.5f - sqrtf(420.25f - 2.0f * (float)idx));
        while (20 * w - (w * (w - 1)) / 2 > idx) --w;
        while (20 * (w + 1) - ((w + 1) * w) / 2 <= idx) ++w;
        int v = w + (idx - (20 * w - (w * (w - 1)) / 2));
        int d = v - w;
        float s = lag[d];
        for (int u = 1; u <= w; ++u)
            s += xs[NW - 1 + u] * xs[NW - 1 + u + d] - xs[u - 1] * xs[u - 1 + d];
        float cv = (s - (float)NW * mw[w] * mw[v]) * (1.f / (float)(NW - 1));
        Cm[w][v] = cv; Cm[v][w] = cv;
    }
    __syncthreads();

    // ---------- phase 2: Tg = C*G, S2 = G^T*Tg -> scratch ----------
    for (int t = tid; t < WINW * D2; t += 128) {
        int w = t >> 3, c = t & 7;
        float s = 0.f;
        #pragma unroll
        for (int v2 = 0; v2 < WINW; ++v2) s = fmaf(Cm[w][v2], Gs[v2 * 8 + c], s);
        Tg[w][c] = s;
    }
    __syncthreads();
    if (tid < 64) {
        int a = tid >> 3, c = tid & 7;
        float s = 0.f;
        #pragma unroll
        for (int w = 0; w < WINW; ++w) s = fmaf(Gs[w * 8 + a], Tg[w][c], s);
        g_S2[b * 64 + tid] = s;
    }
}

// ---------------------------------------------------------------------------
// Jacobi rotation
// ---------------------------------------------------------------------------
__device__ __forceinline__ void jrot(float app, float aqq, float apq,
                                     float& cc, float& ss, float& tt)
{
    float dn = 2.f * apq;
    dn += (dn >= 0.f ? 1e-38f : -1e-38f);
    float th = __fdividef(aqq - app, dn);
    th = fminf(fmaxf(th, -1e18f), 1e18f);
    tt = __fdividef(1.f, fabsf(th) + sqrtf(fmaf(th, th, 1.f)));
    if (th < 0.f) tt = -tt;
    cc = rsqrtf(fmaf(tt, tt, 1.f));
    ss = tt * cc;
}

// ---------------------------------------------------------------------------
// Kernel 2: 4 rows per warp, static-schedule column-register Jacobi (R3 path)
// ---------------------------------------------------------------------------
__global__ __launch_bounds__(256)
void radar_eig_kernel(const float* __restrict__ gWl,
                      const float* __restrict__ gbl,
                      float* __restrict__ out, int B)
{
    __shared__ float wls[192];
    __shared__ float bls[3];

    const int tid = threadIdx.x, wp = tid >> 5, l = tid & 31;
    const int g = l >> 3, j = l & 7, gb = g << 3;
    const unsigned FULL = 0xffffffffu;

    for (int i = tid; i < 192; i += 256) wls[i] = gWl[i];
    if (tid < 3) bls[tid] = gbl[tid];
    __syncthreads();

    int row = blockIdx.x * 32 + wp * 4 + g;
    if (row > B - 1) row = B - 1;

    // lane j holds column j of S2 (symmetric: row j contiguous)
    float a[8];
    {
        const float4* p = reinterpret_cast<const float4*>(g_S2 + row * 64 + j * 8);
        float4 q0 = p[0], q1 = p[1];
        a[0]=q0.x; a[1]=q0.y; a[2]=q0.z; a[3]=q0.w;
        a[4]=q1.x; a[5]=q1.y; a[6]=q1.z; a[7]=q1.w;
    }
    float v[8];
    #pragma unroll
    for (int i = 0; i < 8; ++i) v[i] = (i == j) ? 1.f : 0.f;
    float dg = a[j];

    constexpr int P[7][4] = {{0,1,2,3},{0,2,3,4},{0,1,4,5},{0,2,1,6},
                             {0,3,2,1},{0,4,3,1},{0,5,1,2}};
    constexpr int Q[7][4] = {{7,6,5,4},{1,7,6,5},{2,3,7,6},{3,4,5,7},
                             {4,5,6,7},{5,6,7,2},{6,7,4,3}};
    constexpr unsigned PRT[7] = {
        (7u<<0)|(6u<<3)|(5u<<6)|(4u<<9)|(3u<<12)|(2u<<15)|(1u<<18)|(0u<<21),
        (1u<<0)|(0u<<3)|(7u<<6)|(6u<<9)|(5u<<12)|(4u<<15)|(3u<<18)|(2u<<21),
        (2u<<0)|(3u<<3)|(0u<<6)|(1u<<9)|(7u<<12)|(6u<<15)|(5u<<18)|(4u<<21),
        (3u<<0)|(5u<<3)|(4u<<6)|(0u<<9)|(2u<<12)|(1u<<15)|(7u<<18)|(6u<<21),
        (4u<<0)|(7u<<3)|(6u<<6)|(5u<<9)|(0u<<12)|(3u<<15)|(2u<<18)|(1u<<21),
        (5u<<0)|(2u<<3)|(1u<<6)|(7u<<9)|(6u<<12)|(0u<<15)|(4u<<18)|(3u<<21),
        (6u<<0)|(4u<<3)|(3u<<6)|(2u<<9)|(1u<<12)|(7u<<15)|(0u<<18)|(5u<<21)};
    constexpr unsigned PIX[7] = {
        (0u<<0)|(1u<<2)|(2u<<4)|(3u<<6)|(3u<<8)|(2u<<10)|(1u<<12)|(0u<<14),
        (0u<<0)|(0u<<2)|(1u<<4)|(2u<<6)|(3u<<8)|(3u<<10)|(2u<<12)|(1u<<14),
        (0u<<0)|(1u<<2)|(0u<<4)|(1u<<6)|(2u<<8)|(3u<<10)|(3u<<12)|(2u<<14),
        (0u<<0)|(2u<<2)|(1u<<4)|(0u<<6)|(1u<<8)|(2u<<10)|(3u<<12)|(3u<<14),
        (0u<<0)|(3u<<2)|(2u<<4)|(1u<<6)|(0u<<8)|(1u<<10)|(2u<<12)|(3u<<14),
        (0u<<0)|(3u<<2)|(3u<<4)|(2u<<6)|(1u<<8)|(0u<<10)|(1u<<12)|(2u<<14),
        (0u<<0)|(2u<<2)|(3u<<4)|(3u<<6)|(2u<<8)|(1u<<10)|(0u<<12)|(1u<<14)};

    #pragma unroll 1
    for (int sweep = 0; sweep < 4; ++sweep) {
        #pragma unroll
        for (int rr = 0; rr < 7; ++rr) {
            float ck[4], sk[4], tk[4], ak[4];
            #pragma unroll
            for (int k = 0; k < 4; ++k) {
                const int p = P[rr][k], q = Q[rr][k];
                float app = __shfl_sync(FULL, dg,   gb + p);
                float aqq = __shfl_sync(FULL, dg,   gb + q);
                float apq = __shfl_sync(FULL, a[p], gb + q);
                jrot(app, aqq, apq, ck[k], sk[k], tk[k]);
                ak[k] = apq;
                float tp = a[p], tq = a[q];
                a[p] = fmaf(ck[k], tp, -sk[k] * tq);
                a[q] = fmaf(sk[k], tp,  ck[k] * tq);
            }
            int prt = (PRT[rr] >> (3 * j)) & 7;
            int pix = (PIX[rr] >> (2 * j)) & 3;
            float cj = (pix==0)?ck[0]:(pix==1)?ck[1]:(pix==2)?ck[2]:ck[3];
            float sj = (pix==0)?sk[0]:(pix==1)?sk[1]:(pix==2)?sk[2]:sk[3];
            float tj = (pix==0)?tk[0]:(pix==1)?tk[1]:(pix==2)?tk[2]:tk[3];
            float aj = (pix==0)?ak[0]:(pix==1)?ak[1]:(pix==2)?ak[2]:ak[3];
            bool  isp = j < prt;
            float so  = isp ? -sj : sj;
            int   src = gb + prt;
            #pragma unroll
            for (int i = 0; i < 8; ++i) {
                float oa = __shfl_sync(FULL, a[i], src);
                float ov = __shfl_sync(FULL, v[i], src);
                a[i] = fmaf(cj, a[i], so * oa);
                v[i] = fmaf(cj, v[i], so * ov);
            }
            dg = fmaf(isp ? -tj : tj, aj, dg);
        }
    }

    // head: out_t = sum_k log(l_k) * v_k^T M_t v_k  (lane j owns eigvec j)
    float lg = __logf(fmaxf(dg, 1e-30f));
    float qr[3];
    #pragma unroll
    for (int t = 0; t < 3; ++t) {
        float acc = 0.f;
        #pragma unroll
        for (int i = 0; i < 8; ++i) {
            float wv = 0.f;
            #pragma unroll
            for (int jj = 0; jj < 8; ++jj)
                wv = fmaf(wls[t * 64 + i * 8 + jj], v[jj], wv);
            acc = fmaf(v[i], wv, acc);
        }
        qr[t] = acc * lg;
    }
    #pragma unroll
    for (int t = 0; t < 3; ++t) {
        qr[t] += __shfl_xor_sync(FULL, qr[t], 1);
        qr[t] += __shfl_xor_sync(FULL, qr[t], 2);
        qr[t] += __shfl_xor_sync(FULL, qr[t], 4);
    }
    if (j == 0) {
        out[row * 3 + 0] = qr[0] + bls[0];
        out[row * 3 + 1] = qr[1] + bls[1];
        out[row * 3 + 2] = qr[2] + bls[2];
    }
}

extern "C" void kernel_launch(void* const* d_in, const int* in_sizes, int n_in,
                              void* d_out, int out_size)
{
    const float* x    = (const float*)d_in[0];
    const float* W1   = (const float*)d_in[1];
    const float* W2   = (const float*)d_in[2];
    const float* Wlin = (const float*)d_in[3];
    const float* blin = (const float*)d_in[4];
    float* out = (float*)d_out;

    const int B = in_sizes[0] / TLEN;     // 8192
    radar_cov_kernel<<<B, 128>>>(x, W1, W2);
    radar_eig_kernel<<<(B + 31) / 32, 256>>>(Wlin, blin, out, B);
}

// round 9
// speedup vs baseline: 2.1856x; 1.4845x over previous
#include <cuda_runtime.h>

// RadarNet R9: two kernels.
// K1: ONE WARP PER ROW (8 warps/block, no block barriers after weight setup):
//     x -> lag sums (reg-resident) -> means -> C diag scans -> S2 = G^T C G.
// K2: 4 rows/warp static-schedule Jacobi (R8-proven) with V stored as ROWS
//     (column rotations become lane-local; 8 fewer shuffles/round) + one
//     8x8 XOR-transpose at the end; head via quadratic forms.

namespace {
constexpr int   TLEN = 512;
constexpr int   WINW = 20;
constexpr int   NW   = 493;
constexpr int   MAXB = 8192;
}

__device__ float g_S2[MAXB * 64];

// ---------------------------------------------------------------------------
// Kernel 1: covariance + S2, one warp per row
// ---------------------------------------------------------------------------
__global__ __launch_bounds__(256)
void radar_cov_kernel(const float* __restrict__ gx,
                      const float* __restrict__ gW1,
                      const float* __restrict__ gW2)
{
    __shared__ float W1s[320], W2s[128], Gs[160];
    __shared__ __align__(16) float xs[8][544];
    __shared__ float Cm[8][WINW][WINW + 1];
    __shared__ float Tgs[8][160];
    __shared__ float lagS[8][24];
    __shared__ float mwS[8][WINW];

    const int tid = threadIdx.x, wp = tid >> 5, l = tid & 31;
    const int b = blockIdx.x * 8 + wp;
    const unsigned FULL = 0xffffffffu;

    // ---- per-warp x load (own slice only) ----
    {
        const float4* gx4 = reinterpret_cast<const float4*>(gx + b * TLEN);
        float4* xs4 = reinterpret_cast<float4*>(xs[wp]);
        #pragma unroll
        for (int q = 0; q < 4; ++q) xs4[l + 32 * q] = gx4[l + 32 * q];
        if (l < 8) xs4[128 + l] = make_float4(0.f, 0.f, 0.f, 0.f);
    }

    // ---- block-cooperative weights + G = W1@W2 (only block syncs) ----
    for (int i = tid; i < 320; i += 256) W1s[i] = gW1[i];
    if (tid < 128) W2s[tid] = gW2[tid];
    __syncthreads();
    if (tid < 160) {
        int w = tid >> 3, c = tid & 7;
        float s = 0.f;
        #pragma unroll
        for (int k = 0; k < 16; ++k) s = fmaf(W1s[w * 16 + k], W2s[k * 8 + c], s);
        Gs[tid] = s;
    }
    __syncthreads();

    // ---- lag accumulation: lane l handles n in [16l, 16l+16) ----
    float xv[36];
    {
        const float4* base = reinterpret_cast<const float4*>(xs[wp] + 16 * l);
        #pragma unroll
        for (int q = 0; q < 9; ++q) {
            float4 t = base[q];
            xv[4*q+0] = t.x; xv[4*q+1] = t.y; xv[4*q+2] = t.z; xv[4*q+3] = t.w;
        }
    }
    float acc[21];
    #pragma unroll
    for (int d = 0; d < 21; ++d) acc[d] = 0.f;
    {
        const int nb = 16 * l;
        #pragma unroll
        for (int k = 0; k < 16; ++k) {
            if (nb + k < NW) {
                float xk = xv[k];
                #pragma unroll
                for (int d = 0; d < WINW; ++d) acc[d] = fmaf(xk, xv[k + d], acc[d]);
                acc[20] += xk;
            }
        }
    }
    // warp butterfly -> lane 0 stores 21 lag totals
    #pragma unroll
    for (int d = 0; d < 21; ++d) {
        float v = acc[d];
        #pragma unroll
        for (int o = 16; o; o >>= 1) v += __shfl_down_sync(FULL, v, o);
        if (l == 0) lagS[wp][d] = v;
    }
    __syncwarp();

    // ---- window means via warp prefix scan ----
    {
        float sum0 = lagS[wp][20];
        float val = (l >= 1 && l < WINW) ? (xs[wp][NW - 1 + l] - xs[wp][l - 1]) : 0.f;
        #pragma unroll
        for (int o = 1; o < 32; o <<= 1) {
            float t = __shfl_up_sync(FULL, val, o);
            if (l >= o) val += t;
        }
        if (l < WINW) mwS[wp][l] = (sum0 + val) * (1.f / (float)NW);
    }
    __syncwarp();

    // ---- C via 20 diagonal scans (lane d owns diagonal d) ----
    if (l < WINW) {
        const int d = l;
        const float inv = 1.f / (float)(NW - 1);
        float s = lagS[wp][d];
        float cv = (s - (float)NW * mwS[wp][0] * mwS[wp][d]) * inv;
        Cm[wp][0][d] = cv; Cm[wp][d][0] = cv;
        #pragma unroll 1
        for (int w = 1; w + d < WINW; ++w) {
            s += xs[wp][NW - 1 + w] * xs[wp][NW - 1 + w + d]
               - xs[wp][w - 1]      * xs[wp][w - 1 + d];
            cv = (s - (float)NW * mwS[wp][w] * mwS[wp][w + d]) * inv;
            Cm[wp][w][w + d] = cv; Cm[wp][w + d][w] = cv;
        }
    }
    __syncwarp();

    // ---- Tg = C*G : lane (wg,c), G column c in registers ----
    {
        const int wg = l >> 3, c = l & 7;
        float Gcol[WINW];
        #pragma unroll
        for (int v = 0; v < WINW; ++v) Gcol[v] = Gs[v * 8 + c];
        #pragma unroll
        for (int t = 0; t < 5; ++t) {
            const int w = wg + 4 * t;
            float s = 0.f;
            #pragma unroll
            for (int v = 0; v < WINW; ++v) s = fmaf(Cm[wp][w][v], Gcol[v], s);
            Tgs[wp][w * 8 + c] = s;
        }
    }
    __syncwarp();

    // ---- S2 = G^T * Tg -> scratch (2 entries per lane, coalesced store) ----
    #pragma unroll
    for (int h = 0; h < 2; ++h) {
        const int e = l + 32 * h;
        const int a = e >> 3, c = e & 7;
        float s = 0.f;
        #pragma unroll
        for (int w = 0; w < WINW; ++w) s = fmaf(Gs[w * 8 + a], Tgs[wp][w * 8 + c], s);
        g_S2[b * 64 + e] = s;
    }
}

// ---------------------------------------------------------------------------
// Jacobi rotation
// ---------------------------------------------------------------------------
__device__ __forceinline__ void jrot(float app, float aqq, float apq,
                                     float& cc, float& ss, float& tt)
{
    float dn = 2.f * apq;
    dn += (dn >= 0.f ? 1e-38f : -1e-38f);
    float th = __fdividef(aqq - app, dn);
    th = fminf(fmaxf(th, -1e18f), 1e18f);
    tt = __fdividef(1.f, fabsf(th) + sqrtf(fmaf(th, th, 1.f)));
    if (th < 0.f) tt = -tt;
    cc = rsqrtf(fmaf(tt, tt, 1.f));
    ss = tt * cc;
}

// ---------------------------------------------------------------------------
// Kernel 2: 4 rows/warp static Jacobi, V stored as rows (lane-local updates)
// ---------------------------------------------------------------------------
__global__ __launch_bounds__(256)
void radar_eig_kernel(const float* __restrict__ gWl,
                      const float* __restrict__ gbl,
                      float* __restrict__ out, int B)
{
    __shared__ float wls[192];
    __shared__ float bls[3];

    const int tid = threadIdx.x, wp = tid >> 5, l = tid & 31;
    const int g = l >> 3, j = l & 7, gb = g << 3;
    const unsigned FULL = 0xffffffffu;

    for (int i = tid; i < 192; i += 256) wls[i] = gWl[i];
    if (tid < 3) bls[tid] = gbl[tid];
    __syncthreads();

    int row = blockIdx.x * 32 + wp * 4 + g;
    if (row > B - 1) row = B - 1;

    float a[8];
    {
        const float4* p = reinterpret_cast<const float4*>(g_S2 + row * 64 + j * 8);
        float4 q0 = p[0], q1 = p[1];
        a[0]=q0.x; a[1]=q0.y; a[2]=q0.z; a[3]=q0.w;
        a[4]=q1.x; a[5]=q1.y; a[6]=q1.z; a[7]=q1.w;
    }
    float v[8];                              // ROW j of V
    #pragma unroll
    for (int i = 0; i < 8; ++i) v[i] = (i == j) ? 1.f : 0.f;
    float dg = a[j];

    constexpr int P[7][4] = {{0,1,2,3},{0,2,3,4},{0,1,4,5},{0,2,1,6},
                             {0,3,2,1},{0,4,3,1},{0,5,1,2}};
    constexpr int Q[7][4] = {{7,6,5,4},{1,7,6,5},{2,3,7,6},{3,4,5,7},
                             {4,5,6,7},{5,6,7,2},{6,7,4,3}};
    constexpr unsigned PRT[7] = {
        (7u<<0)|(6u<<3)|(5u<<6)|(4u<<9)|(3u<<12)|(2u<<15)|(1u<<18)|(0u<<21),
        (1u<<0)|(0u<<3)|(7u<<6)|(6u<<9)|(5u<<12)|(4u<<15)|(3u<<18)|(2u<<21),
        (2u<<0)|(3u<<3)|(0u<<6)|(1u<<9)|(7u<<12)|(6u<<15)|(5u<<18)|(4u<<21),
        (3u<<0)|(5u<<3)|(4u<<6)|(0u<<9)|(2u<<12)|(1u<<15)|(7u<<18)|(6u<<21),
        (4u<<0)|(7u<<3)|(6u<<6)|(5u<<9)|(0u<<12)|(3u<<15)|(2u<<18)|(1u<<21),
        (5u<<0)|(2u<<3)|(1u<<6)|(7u<<9)|(6u<<12)|(0u<<15)|(4u<<18)|(3u<<21),
        (6u<<0)|(4u<<3)|(3u<<6)|(2u<<9)|(1u<<12)|(7u<<15)|(0u<<18)|(5u<<21)};
    constexpr unsigned PIX[7] = {
        (0u<<0)|(1u<<2)|(2u<<4)|(3u<<6)|(3u<<8)|(2u<<10)|(1u<<12)|(0u<<14),
        (0u<<0)|(0u<<2)|(1u<<4)|(2u<<6)|(3u<<8)|(3u<<10)|(2u<<12)|(1u<<14),
        (0u<<0)|(1u<<2)|(0u<<4)|(1u<<6)|(2u<<8)|(3u<<10)|(3u<<12)|(2u<<14),
        (0u<<0)|(2u<<2)|(1u<<4)|(0u<<6)|(1u<<8)|(2u<<10)|(3u<<12)|(3u<<14),
        (0u<<0)|(3u<<2)|(2u<<4)|(1u<<6)|(0u<<8)|(1u<<10)|(2u<<12)|(3u<<14),
        (0u<<0)|(3u<<2)|(3u<<4)|(2u<<6)|(1u<<8)|(0u<<10)|(1u<<12)|(2u<<14),
        (0u<<0)|(2u<<2)|(3u<<4)|(3u<<6)|(2u<<8)|(1u<<10)|(0u<<12)|(1u<<14)};

    #pragma unroll 1
    for (int sweep = 0; sweep < 4; ++sweep) {
        #pragma unroll
        for (int rr = 0; rr < 7; ++rr) {
            float ck[4], sk[4], tk[4], ak[4];
            #pragma unroll
            for (int k = 0; k < 4; ++k) {
                const int p = P[rr][k], q = Q[rr][k];
                float app = __shfl_sync(FULL, dg,   gb + p);
                float aqq = __shfl_sync(FULL, dg,   gb + q);
                float apq = __shfl_sync(FULL, a[p], gb + q);
                jrot(app, aqq, apq, ck[k], sk[k], tk[k]);
                ak[k] = apq;
                // A row update (in-lane)
                float tp = a[p], tq = a[q];
                a[p] = fmaf(ck[k], tp, -sk[k] * tq);
                a[q] = fmaf(sk[k], tp,  ck[k] * tq);
                // V column update (in-lane: V stored as rows)
                float vp = v[p], vq = v[q];
                v[p] = fmaf(ck[k], vp, -sk[k] * vq);
                v[q] = fmaf(sk[k], vp,  ck[k] * vq);
            }
            // A column update (cross-lane)
            int prt = (PRT[rr] >> (3 * j)) & 7;
            int pix = (PIX[rr] >> (2 * j)) & 3;
            float cj = (pix==0)?ck[0]:(pix==1)?ck[1]:(pix==2)?ck[2]:ck[3];
            float sj = (pix==0)?sk[0]:(pix==1)?sk[1]:(pix==2)?sk[2]:sk[3];
            float tj = (pix==0)?tk[0]:(pix==1)?tk[1]:(pix==2)?tk[2]:tk[3];
            float aj = (pix==0)?ak[0]:(pix==1)?ak[1]:(pix==2)?ak[2]:ak[3];
            bool  isp = j < prt;
            float so  = isp ? -sj : sj;
            int   src = gb + prt;
            #pragma unroll
            for (int i = 0; i < 8; ++i) {
                float oa = __shfl_sync(FULL, a[i], src);
                a[i] = fmaf(cj, a[i], so * oa);
            }
            dg = fmaf(isp ? -tj : tj, aj, dg);
        }
    }

    // transpose V (rows -> columns) within the 8-lane group: 12 shuffles
    #pragma unroll
    for (int m = 1; m < 8; m <<= 1) {
        #pragma unroll
        for (int i = 0; i < 8; ++i) {
            if (i & m) continue;
            const int ip = i | m;
            float send = (j & m) ? v[i] : v[ip];
            float recv = __shfl_xor_sync(FULL, send, m);
            if (j & m) v[i] = recv; else v[ip] = recv;
        }
    }

    // head: out_t = sum_k log(l_k) * v_k^T M_t v_k  (lane j owns eigvec j)
    float lg = __logf(fmaxf(dg, 1e-30f));
    float qr[3];
    #pragma unroll
    for (int t = 0; t < 3; ++t) {
        float acc = 0.f;
        #pragma unroll
        for (int i = 0; i < 8; ++i) {
            float wv = 0.f;
            #pragma unroll
            for (int jj = 0; jj < 8; ++jj)
                wv = fmaf(wls[t * 64 + i * 8 + jj], v[jj], wv);
            acc = fmaf(v[i], wv, acc);
        }
        qr[t] = acc * lg;
    }
    #pragma unroll
    for (int t = 0; t < 3; ++t) {
        qr[t] += __shfl_xor_sync(FULL, qr[t], 1);
        qr[t] += __shfl_xor_sync(FULL, qr[t], 2);
        qr[t] += __shfl_xor_sync(FULL, qr[t], 4);
    }
    if (j == 0) {
        out[row * 3 + 0] = qr[0] + bls[0];
        out[row * 3 + 1] = qr[1] + bls[1];
        out[row * 3 + 2] = qr[2] + bls[2];
    }
}

extern "C" void kernel_launch(void* const* d_in, const int* in_sizes, int n_in,
                              void* d_out, int out_size)
{
    const float* x    = (const float*)d_in[0];
    const float* W1   = (const float*)d_in[1];
    const float* W2   = (const float*)d_in[2];
    const float* Wlin = (const float*)d_in[3];
    const float* blin = (const float*)d_in[4];
    float* out = (float*)d_out;

    const int B = in_sizes[0] / TLEN;     // 8192
    radar_cov_kernel<<<B / 8, 256>>>(x, W1, W2);
    radar_eig_kernel<<<(B + 31) / 32, 256>>>(Wlin, blin, out, B);
}

// round 10
// speedup vs baseline: 2.5219x; 1.1539x over previous
#include <cuda_runtime.h>

// RadarNet R10: two kernels.
// K1: one warp per row (R9-proven, unchanged): x -> lags -> means -> C -> S2.
// K2: 4 rows/warp static Jacobi; NEW: each lane computes only ITS pair's
//     rotation (2x redundancy, was 8x), distributes (c,s) by 8 shuffles.
//     V stored as rows (in-lane updates) + XOR-transpose; quadratic-form head.

namespace {
constexpr int   TLEN = 512;
constexpr int   WINW = 20;
constexpr int   NW   = 493;
constexpr int   MAXB = 8192;
}

__device__ float g_S2[MAXB * 64];

// ---------------------------------------------------------------------------
// Kernel 1: covariance + S2, one warp per row (R9-proven)
// ---------------------------------------------------------------------------
__global__ __launch_bounds__(256)
void radar_cov_kernel(const float* __restrict__ gx,
                      const float* __restrict__ gW1,
                      const float* __restrict__ gW2)
{
    __shared__ float W1s[320], W2s[128], Gs[160];
    __shared__ __align__(16) float xs[8][544];
    __shared__ float Cm[8][WINW][WINW + 1];
    __shared__ float Tgs[8][160];
    __shared__ float lagS[8][24];
    __shared__ float mwS[8][WINW];

    const int tid = threadIdx.x, wp = tid >> 5, l = tid & 31;
    const int b = blockIdx.x * 8 + wp;
    const unsigned FULL = 0xffffffffu;

    {
        const float4* gx4 = reinterpret_cast<const float4*>(gx + b * TLEN);
        float4* xs4 = reinterpret_cast<float4*>(xs[wp]);
        #pragma unroll
        for (int q = 0; q < 4; ++q) xs4[l + 32 * q] = gx4[l + 32 * q];
        if (l < 8) xs4[128 + l] = make_float4(0.f, 0.f, 0.f, 0.f);
    }

    for (int i = tid; i < 320; i += 256) W1s[i] = gW1[i];
    if (tid < 128) W2s[tid] = gW2[tid];
    __syncthreads();
    if (tid < 160) {
        int w = tid >> 3, c = tid & 7;
        float s = 0.f;
        #pragma unroll
        for (int k = 0; k < 16; ++k) s = fmaf(W1s[w * 16 + k], W2s[k * 8 + c], s);
        Gs[tid] = s;
    }
    __syncthreads();

    float xv[36];
    {
        const float4* base = reinterpret_cast<const float4*>(xs[wp] + 16 * l);
        #pragma unroll
        for (int q = 0; q < 9; ++q) {
            float4 t = base[q];
            xv[4*q+0] = t.x; xv[4*q+1] = t.y; xv[4*q+2] = t.z; xv[4*q+3] = t.w;
        }
    }
    float acc[21];
    #pragma unroll
    for (int d = 0; d < 21; ++d) acc[d] = 0.f;
    {
        const int nb = 16 * l;
        #pragma unroll
        for (int k = 0; k < 16; ++k) {
            if (nb + k < NW) {
                float xk = xv[k];
                #pragma unroll
                for (int d = 0; d < WINW; ++d) acc[d] = fmaf(xk, xv[k + d], acc[d]);
                acc[20] += xk;
            }
        }
    }
    #pragma unroll
    for (int d = 0; d < 21; ++d) {
        float v = acc[d];
        #pragma unroll
        for (int o = 16; o; o >>= 1) v += __shfl_down_sync(FULL, v, o);
        if (l == 0) lagS[wp][d] = v;
    }
    __syncwarp();

    {
        float sum0 = lagS[wp][20];
        float val = (l >= 1 && l < WINW) ? (xs[wp][NW - 1 + l] - xs[wp][l - 1]) : 0.f;
        #pragma unroll
        for (int o = 1; o < 32; o <<= 1) {
            float t = __shfl_up_sync(FULL, val, o);
            if (l >= o) val += t;
        }
        if (l < WINW) mwS[wp][l] = (sum0 + val) * (1.f / (float)NW);
    }
    __syncwarp();

    if (l < WINW) {
        const int d = l;
        const float inv = 1.f / (float)(NW - 1);
        float s = lagS[wp][d];
        float cv = (s - (float)NW * mwS[wp][0] * mwS[wp][d]) * inv;
        Cm[wp][0][d] = cv; Cm[wp][d][0] = cv;
        #pragma unroll 1
        for (int w = 1; w + d < WINW; ++w) {
            s += xs[wp][NW - 1 + w] * xs[wp][NW - 1 + w + d]
               - xs[wp][w - 1]      * xs[wp][w - 1 + d];
            cv = (s - (float)NW * mwS[wp][w] * mwS[wp][w + d]) * inv;
            Cm[wp][w][w + d] = cv; Cm[wp][w + d][w] = cv;
        }
    }
    __syncwarp();

    {
        const int wg = l >> 3, c = l & 7;
        float Gcol[WINW];
        #pragma unroll
        for (int v = 0; v < WINW; ++v) Gcol[v] = Gs[v * 8 + c];
        #pragma unroll
        for (int t = 0; t < 5; ++t) {
            const int w = wg + 4 * t;
            float s = 0.f;
            #pragma unroll
            for (int v = 0; v < WINW; ++v) s = fmaf(Cm[wp][w][v], Gcol[v], s);
            Tgs[wp][w * 8 + c] = s;
        }
    }
    __syncwarp();

    #pragma unroll
    for (int h = 0; h < 2; ++h) {
        const int e = l + 32 * h;
        const int a = e >> 3, c = e & 7;
        float s = 0.f;
        #pragma unroll
        for (int w = 0; w < WINW; ++w) s = fmaf(Gs[w * 8 + a], Tgs[wp][w * 8 + c], s);
        g_S2[b * 64 + e] = s;
    }
}

// ---------------------------------------------------------------------------
// Jacobi rotation
// ---------------------------------------------------------------------------
__device__ __forceinline__ void jrot(float app, float aqq, float apq,
                                     float& cc, float& ss, float& tt)
{
    float dn = 2.f * apq;
    dn += (dn >= 0.f ? 1e-38f : -1e-38f);
    float th = __fdividef(aqq - app, dn);
    th = fminf(fmaxf(th, -1e18f), 1e18f);
    tt = __fdividef(1.f, fabsf(th) + sqrtf(fmaf(th, th, 1.f)));
    if (th < 0.f) tt = -tt;
    cc = rsqrtf(fmaf(tt, tt, 1.f));
    ss = tt * cc;
}

// ---------------------------------------------------------------------------
// Kernel 2: 4 rows/warp static Jacobi, per-pair rotation dedup
// ---------------------------------------------------------------------------
__global__ __launch_bounds__(256)
void radar_eig_kernel(const float* __restrict__ gWl,
                      const float* __restrict__ gbl,
                      float* __restrict__ out, int B)
{
    __shared__ float wls[192];
    __shared__ float bls[3];

    const int tid = threadIdx.x, wp = tid >> 5, l = tid & 31;
    const int g = l >> 3, j = l & 7, gb = g << 3;
    const unsigned FULL = 0xffffffffu;

    for (int i = tid; i < 192; i += 256) wls[i] = gWl[i];
    if (tid < 3) bls[tid] = gbl[tid];
    __syncthreads();

    int row = blockIdx.x * 32 + wp * 4 + g;
    if (row > B - 1) row = B - 1;

    float a[8];
    {
        const float4* p = reinterpret_cast<const float4*>(g_S2 + row * 64 + j * 8);
        float4 q0 = p[0], q1 = p[1];
        a[0]=q0.x; a[1]=q0.y; a[2]=q0.z; a[3]=q0.w;
        a[4]=q1.x; a[5]=q1.y; a[6]=q1.z; a[7]=q1.w;
    }
    float v[8];                              // ROW j of V
    #pragma unroll
    for (int i = 0; i < 8; ++i) v[i] = (i == j) ? 1.f : 0.f;
    float dg = a[j];

    constexpr int P[7][4] = {{0,1,2,3},{0,2,3,4},{0,1,4,5},{0,2,1,6},
                             {0,3,2,1},{0,4,3,1},{0,5,1,2}};
    constexpr int Q[7][4] = {{7,6,5,4},{1,7,6,5},{2,3,7,6},{3,4,5,7},
                             {4,5,6,7},{5,6,7,2},{6,7,4,3}};
    constexpr unsigned PRT[7] = {
        (7u<<0)|(6u<<3)|(5u<<6)|(4u<<9)|(3u<<12)|(2u<<15)|(1u<<18)|(0u<<21),
        (1u<<0)|(0u<<3)|(7u<<6)|(6u<<9)|(5u<<12)|(4u<<15)|(3u<<18)|(2u<<21),
        (2u<<0)|(3u<<3)|(0u<<6)|(1u<<9)|(7u<<12)|(6u<<15)|(5u<<18)|(4u<<21),
        (3u<<0)|(5u<<3)|(4u<<6)|(0u<<9)|(2u<<12)|(1u<<15)|(7u<<18)|(6u<<21),
        (4u<<0)|(7u<<3)|(6u<<6)|(5u<<9)|(0u<<12)|(3u<<15)|(2u<<18)|(1u<<21),
        (5u<<0)|(2u<<3)|(1u<<6)|(7u<<9)|(6u<<12)|(0u<<15)|(4u<<18)|(3u<<21),
        (6u<<0)|(4u<<3)|(3u<<6)|(2u<<9)|(1u<<12)|(7u<<15)|(0u<<18)|(5u<<21)};

    #pragma unroll 1
    for (int sweep = 0; sweep < 4; ++sweep) {
        #pragma unroll
        for (int rr = 0; rr < 7; ++rr) {
            const int prt = (PRT[rr] >> (3 * j)) & 7;
            const bool isp = j < prt;
            const int src = gb + prt;

            // own pair's rotation inputs (each pair computed by its 2 lanes)
            float apair = a[0];
            #pragma unroll
            for (int i = 1; i < 8; ++i) if (prt == i) apair = a[i];
            float dgo    = __shfl_sync(FULL, dg,    src);
            float apairo = __shfl_sync(FULL, apair, src);
            float apq = isp ? apairo : apair;      // A[p][q] (identical in both lanes)
            float app = isp ? dg  : dgo;
            float aqq = isp ? dgo : dg;
            float c, s, t;
            jrot(app, aqq, apq, c, s, t);

            // distribute the 4 pair-rotations to all lanes
            float ck[4], sk[4];
            #pragma unroll
            for (int k = 0; k < 4; ++k) {
                ck[k] = __shfl_sync(FULL, c, gb + P[rr][k]);
                sk[k] = __shfl_sync(FULL, s, gb + P[rr][k]);
            }

            // in-lane row update (A <- J^T A) and V column update (V <- V J)
            #pragma unroll
            for (int k = 0; k < 4; ++k) {
                const int p = P[rr][k], q = Q[rr][k];
                float tp = a[p], tq = a[q];
                a[p] = fmaf(ck[k], tp, -sk[k] * tq);
                a[q] = fmaf(sk[k], tp,  ck[k] * tq);
                float vp = v[p], vq = v[q];
                v[p] = fmaf(ck[k], vp, -sk[k] * vq);
                v[q] = fmaf(sk[k], vp,  ck[k] * vq);
            }

            // cross-lane column update (A <- A J), own (c,s)
            float so = isp ? -s : s;
            #pragma unroll
            for (int i = 0; i < 8; ++i) {
                float oa = __shfl_sync(FULL, a[i], src);
                a[i] = fmaf(c, a[i], so * oa);
            }
            dg = fmaf(isp ? -t : t, apq, dg);
        }
    }

    // transpose V (rows -> columns) within the 8-lane group
    #pragma unroll
    for (int m = 1; m < 8; m <<= 1) {
        #pragma unroll
        for (int i = 0; i < 8; ++i) {
            if (i & m) continue;
            const int ip = i | m;
            float send = (j & m) ? v[i] : v[ip];
            float recv = __shfl_xor_sync(FULL, send, m);
            if (j & m) v[i] = recv; else v[ip] = recv;
        }
    }

    // head: out_t = sum_k log(l_k) * v_k^T M_t v_k
    float lg = __logf(fmaxf(dg, 1e-30f));
    float qr[3];
    #pragma unroll
    for (int t = 0; t < 3; ++t) {
        float acc = 0.f;
        #pragma unroll
        for (int i = 0; i < 8; ++i) {
            float wv = 0.f;
            #pragma unroll
            for (int jj = 0; jj < 8; ++jj)
                wv = fmaf(wls[t * 64 + i * 8 + jj], v[jj], wv);
            acc = fmaf(v[i], wv, acc);
        }
        qr[t] = acc * lg;
    }
    #pragma unroll
    for (int t = 0; t < 3; ++t) {
        qr[t] += __shfl_xor_sync(FULL, qr[t], 1);
        qr[t] += __shfl_xor_sync(FULL, qr[t], 2);
        qr[t] += __shfl_xor_sync(FULL, qr[t], 4);
    }
    if (j == 0) {
        out[row * 3 + 0] = qr[0] + bls[0];
        out[row * 3 + 1] = qr[1] + bls[1];
        out[row * 3 + 2] = qr[2] + bls[2];
    }
}

extern "C" void kernel_launch(void* const* d_in, const int* in_sizes, int n_in,
                              void* d_out, int out_size)
{
    const float* x    = (const float*)d_in[0];
    const float* W1   = (const float*)d_in[1];
    const float* W2   = (const float*)d_in[2];
    const float* Wlin = (const float*)d_in[3];
    const float* blin = (const float*)d_in[4];
    float* out = (float*)d_out;

    const int B = in_sizes[0] / TLEN;     // 8192
    radar_cov_kernel<<<B / 8, 256>>>(x, W1, W2);
    radar_eig_kernel<<<(B + 31) / 32, 256>>>(Wlin, blin, out, B);
}